// round 2
// baseline (speedup 1.0000x reference)
#include <cuda_runtime.h>

#define HID 1024
#define NSAMP 1024
#define TSTEPS 98

// Persistent scratch (allowed: __device__ globals, no allocation)
__device__ float g_W2T[HID * HID];
__device__ float g_W3T[HID * HID];
__device__ float g_fr[3];

// ---------------------------------------------------------------------------
// One-time prep per launch: transpose W2, W3 so spike-row gathers are
// contiguous (W*T[h][j] = W*[j][h]); zero the firing-rate accumulators.
// ---------------------------------------------------------------------------
__global__ void prep_kernel(const float* __restrict__ W2,
                            const float* __restrict__ W3) {
    __shared__ float tile[32][33];
    const float* src = (blockIdx.z == 0) ? W2 : W3;
    float* dst = (blockIdx.z == 0) ? g_W2T : g_W3T;
    int bx = blockIdx.x * 32, by = blockIdx.y * 32;
    tile[threadIdx.y][threadIdx.x] = src[(by + threadIdx.y) * HID + bx + threadIdx.x];
    __syncthreads();
    dst[(bx + threadIdx.y) * HID + by + threadIdx.x] = tile[threadIdx.x][threadIdx.y];
    if (blockIdx.x == 0 && blockIdx.y == 0 && blockIdx.z == 0 &&
        threadIdx.y == 0 && threadIdx.x < 3)
        g_fr[threadIdx.x] = 0.0f;
}

// Deterministic block-wide exclusive scan over 256 threads (8 warps).
// Also returns the block total. Contains two __syncthreads(); the first one
// doubles as the "everyone finished reading the previous spike list" barrier.
static __device__ __forceinline__ void block_scan(int v, int tid, int* s_warp,
                                                  int& excl, int& total) {
    int lane = tid & 31, wid = tid >> 5;
    int x = v;
#pragma unroll
    for (int o = 1; o < 32; o <<= 1) {
        int y = __shfl_up_sync(0xffffffffu, x, o);
        if (lane >= o) x += y;
    }
    __syncthreads();
    if (lane == 31) s_warp[wid] = x;
    __syncthreads();
    int pre = 0, tot = 0;
#pragma unroll
    for (int w = 0; w < 8; w++) {
        int sw = s_warp[w];
        pre += (w < wid) ? sw : 0;
        tot += sw;
    }
    excl = pre + x - v;
    total = tot;
}

// ---------------------------------------------------------------------------
// Persistent per-sample kernel: block n runs all 98 timesteps for sample n.
// 256 threads, each owns 4 contiguous hidden units (j0..j0+3) in every layer.
// All membrane/spike/spike-count state lives in registers.
// ---------------------------------------------------------------------------
__global__ void __launch_bounds__(256) snn_kernel(
    const float* __restrict__ input,
    const float* __restrict__ W1, const float* __restrict__ b1,
    const float* __restrict__ b2, const float* __restrict__ b3,
    const float* __restrict__ W4, const float* __restrict__ b4,
    float* __restrict__ out) {
    __shared__ unsigned short list_s[HID];
    __shared__ int s_warp[8];
    __shared__ float s_red[256];

    const int n = blockIdx.x;
    const int tid = threadIdx.x;
    const int j0 = tid * 4;

    float m1[4] = {0, 0, 0, 0}, m2[4] = {0, 0, 0, 0}, m3[4] = {0, 0, 0, 0};
    float s1[4] = {0, 0, 0, 0}, s2[4] = {0, 0, 0, 0}, s3[4] = {0, 0, 0, 0};
    float ss1[4] = {0, 0, 0, 0}, ss2[4] = {0, 0, 0, 0}, ss3[4] = {0, 0, 0, 0};

    float b1v[4], b2v[4], b3v[4];
#pragma unroll
    for (int k = 0; k < 4; k++) {
        b1v[k] = __ldg(b1 + j0 + k);
        b2v[k] = __ldg(b2 + j0 + k);
        b3v[k] = __ldg(b3 + j0 + k);
    }

    const float* xrow = input + n * 784;
    const float4* W2T4 = reinterpret_cast<const float4*>(g_W2T);
    const float4* W3T4 = reinterpret_cast<const float4*>(g_W3T);

    for (int t = 0; t < TSTEPS; t++) {
        // Faithful (buggy-in-original) input slicing: start = 8t while
        // 8t < T-8, else last 8 pixels of the 784-long row.
        const int start = (t <= 11) ? t * 8 : 776;
        float xv[8];
#pragma unroll
        for (int i = 0; i < 8; i++) xv[i] = __ldg(xrow + start + i);

        // ---------------- layer 1 (mask cycle 2) ----------------
        int cl = 0;
#pragma unroll
        for (int k = 0; k < 4; k++) {
            int h = j0 + k;
            int u = (t - h + 1078) % 98;  // (t - h) mod 98, h <= 1023
            float sn = 0.0f;
            if ((u & 1) == 0) {
                float d = b1v[k];
#pragma unroll
                for (int i = 0; i < 8; i++) d += xv[i] * __ldg(W1 + h * 8 + i);
                m1[k] = m1[k] * 0.5f * (1.0f - s1[k]) + d;
                sn = (m1[k] > 0.5f) ? 1.0f : 0.0f;
            }
            s1[k] = sn;
            ss1[k] += sn;
            cl += (sn != 0.0f);
        }
        int base, cnt;
        block_scan(cl, tid, s_warp, base, cnt);
        {
            int p = base;
#pragma unroll
            for (int k = 0; k < 4; k++)
                if (s1[k] != 0.0f) list_s[p++] = (unsigned short)(j0 + k);
        }
        __syncthreads();

        // ---------------- layer 2 drive: sparse row sum ----------------
        float4 acc = make_float4(b2v[0], b2v[1], b2v[2], b2v[3]);
        {
            int i = 0;
            for (; i + 4 <= cnt; i += 4) {
                int h0 = list_s[i + 0], h1 = list_s[i + 1];
                int h2 = list_s[i + 2], h3 = list_s[i + 3];
                float4 w0 = __ldg(W2T4 + h0 * 256 + tid);
                float4 w1 = __ldg(W2T4 + h1 * 256 + tid);
                float4 w2 = __ldg(W2T4 + h2 * 256 + tid);
                float4 w3 = __ldg(W2T4 + h3 * 256 + tid);
                acc.x += w0.x; acc.y += w0.y; acc.z += w0.z; acc.w += w0.w;
                acc.x += w1.x; acc.y += w1.y; acc.z += w1.z; acc.w += w1.w;
                acc.x += w2.x; acc.y += w2.y; acc.z += w2.z; acc.w += w2.w;
                acc.x += w3.x; acc.y += w3.y; acc.z += w3.z; acc.w += w3.w;
            }
            for (; i < cnt; i++) {
                int h = list_s[i];
                float4 w = __ldg(W2T4 + h * 256 + tid);
                acc.x += w.x; acc.y += w.y; acc.z += w.z; acc.w += w.w;
            }
        }
        float dr2[4] = {acc.x, acc.y, acc.z, acc.w};

        // ---------------- layer 2 update (mask cycle 3) ----------------
        cl = 0;
#pragma unroll
        for (int k = 0; k < 4; k++) {
            int h = j0 + k;
            int u = (t - h + 1078) % 98;
            float sn = 0.0f;
            if (u % 3 == 0) {
                m2[k] = m2[k] * 0.5f * (1.0f - s2[k]) + dr2[k];
                sn = (m2[k] > 0.5f) ? 1.0f : 0.0f;
            }
            s2[k] = sn;
            ss2[k] += sn;
            cl += (sn != 0.0f);
        }
        block_scan(cl, tid, s_warp, base, cnt);
        {
            int p = base;
#pragma unroll
            for (int k = 0; k < 4; k++)
                if (s2[k] != 0.0f) list_s[p++] = (unsigned short)(j0 + k);
        }
        __syncthreads();

        // ---------------- layer 3 drive: sparse row sum ----------------
        float4 acc3 = make_float4(b3v[0], b3v[1], b3v[2], b3v[3]);
        {
            int i = 0;
            for (; i + 4 <= cnt; i += 4) {
                int h0 = list_s[i + 0], h1 = list_s[i + 1];
                int h2 = list_s[i + 2], h3 = list_s[i + 3];
                float4 w0 = __ldg(W3T4 + h0 * 256 + tid);
                float4 w1 = __ldg(W3T4 + h1 * 256 + tid);
                float4 w2 = __ldg(W3T4 + h2 * 256 + tid);
                float4 w3 = __ldg(W3T4 + h3 * 256 + tid);
                acc3.x += w0.x; acc3.y += w0.y; acc3.z += w0.z; acc3.w += w0.w;
                acc3.x += w1.x; acc3.y += w1.y; acc3.z += w1.z; acc3.w += w1.w;
                acc3.x += w2.x; acc3.y += w2.y; acc3.z += w2.z; acc3.w += w2.w;
                acc3.x += w3.x; acc3.y += w3.y; acc3.z += w3.z; acc3.w += w3.w;
            }
            for (; i < cnt; i++) {
                int h = list_s[i];
                float4 w = __ldg(W3T4 + h * 256 + tid);
                acc3.x += w.x; acc3.y += w.y; acc3.z += w.z; acc3.w += w.w;
            }
        }

        // ---------------- layer 3 update (mask cycle 4) ----------------
        float dr3[4] = {acc3.x, acc3.y, acc3.z, acc3.w};
#pragma unroll
        for (int k = 0; k < 4; k++) {
            int h = j0 + k;
            int u = (t - h + 1078) % 98;
            float sn = 0.0f;
            if ((u & 3) == 0) {
                m3[k] = m3[k] * 0.5f * (1.0f - s3[k]) + dr3[k];
                sn = (m3[k] > 0.5f) ? 1.0f : 0.0f;
            }
            s3[k] = sn;
            ss3[k] += sn;
        }
        // layer 4 is linear in ss3 -> deferred to epilogue
    }

    // ------------------------- epilogue -------------------------
    // hidden_spk = ss / T
#pragma unroll
    for (int k = 0; k < 4; k++) {
        out[10240 + 0 * 1048576 + n * HID + j0 + k] = ss1[k] / 98.0f;
        out[10240 + 1 * 1048576 + n * HID + j0 + k] = ss2[k] / 98.0f;
        out[10240 + 2 * 1048576 + n * HID + j0 + k] = ss3[k] / 98.0f;
    }

    // outputs[n] = (ss3 @ W4^T)/T + b4   (== osum/T since osum = ss3@W4^T + T*b4)
#pragma unroll
    for (int o = 0; o < 10; o++) {
        float p = 0.0f;
#pragma unroll
        for (int k = 0; k < 4; k++) p += ss3[k] * __ldg(W4 + o * HID + j0 + k);
        s_red[tid] = p;
        __syncthreads();
        for (int st = 128; st > 0; st >>= 1) {
            if (tid < st) s_red[tid] += s_red[tid + st];
            __syncthreads();
        }
        if (tid == 0) out[n * 10 + o] = s_red[0] / 98.0f + __ldg(b4 + o);
        __syncthreads();
    }

    // layer firing-rate partial sums (exact small integers in fp32)
    float a[3];
    a[0] = ss1[0] + ss1[1] + ss1[2] + ss1[3];
    a[1] = ss2[0] + ss2[1] + ss2[2] + ss2[3];
    a[2] = ss3[0] + ss3[1] + ss3[2] + ss3[3];
#pragma unroll
    for (int l = 0; l < 3; l++) {
        s_red[tid] = a[l];
        __syncthreads();
        for (int st = 128; st > 0; st >>= 1) {
            if (tid < st) s_red[tid] += s_red[tid + st];
            __syncthreads();
        }
        if (tid == 0) atomicAdd(&g_fr[l], s_red[0]);
        __syncthreads();
    }
}

__global__ void finalize_kernel(float* __restrict__ out) {
    // denom = N*H*T = 1024*1024*98 = 102760448 (exactly representable)
    if (threadIdx.x < 3)
        out[3155968 + threadIdx.x] = g_fr[threadIdx.x] / 102760448.0f;
}

extern "C" void kernel_launch(void* const* d_in, const int* in_sizes, int n_in,
                              void* d_out, int out_size) {
    const float* input = (const float*)d_in[0];
    const float* W1 = (const float*)d_in[1];
    const float* b1 = (const float*)d_in[2];
    const float* W2 = (const float*)d_in[3];
    const float* b2 = (const float*)d_in[4];
    const float* W3 = (const float*)d_in[5];
    const float* b3 = (const float*)d_in[6];
    const float* W4 = (const float*)d_in[7];
    const float* b4 = (const float*)d_in[8];
    // d_in[9..11] are mask1..3: regenerated arithmetically in-kernel
    (void)in_sizes; (void)n_in; (void)out_size;

    dim3 pgrid(HID / 32, HID / 32, 2);
    prep_kernel<<<pgrid, dim3(32, 32)>>>(W2, W3);
    snn_kernel<<<NSAMP, 256>>>(input, W1, b1, b2, b3, W4, b4, (float*)d_out);
    finalize_kernel<<<1, 32>>>((float*)d_out);
}

// round 4
// speedup vs baseline: 1.1972x; 1.1972x over previous
#include <cuda_runtime.h>

#define HID 1024
#define NSAMP 1024
#define TSTEPS 98
#define G 8            // samples per CTA
#define NTHR 512       // threads per CTA; each thread owns units 2*tid, 2*tid+1
#define NCTA (NSAMP / G)

__device__ float g_W2T[HID * HID];
__device__ float g_W3T[HID * HID];
__device__ float g_fr[3];

// ---------------------------------------------------------------------------
__global__ void prep_kernel(const float* __restrict__ W2,
                            const float* __restrict__ W3) {
    __shared__ float tile[32][33];
    const float* src = (blockIdx.z == 0) ? W2 : W3;
    float* dst = (blockIdx.z == 0) ? g_W2T : g_W3T;
    int bx = blockIdx.x * 32, by = blockIdx.y * 32;
    tile[threadIdx.y][threadIdx.x] = src[(by + threadIdx.y) * HID + bx + threadIdx.x];
    __syncthreads();
    dst[(bx + threadIdx.y) * HID + by + threadIdx.x] = tile[threadIdx.x][threadIdx.y];
    if (blockIdx.x == 0 && blockIdx.y == 0 && blockIdx.z == 0 &&
        threadIdx.y == 0 && threadIdx.x < 3)
        g_fr[threadIdx.x] = 0.0f;
}

// ---------------------------------------------------------------------------
static __device__ __forceinline__ unsigned long long addf32x2(
    unsigned long long a, unsigned long long b) {
    unsigned long long o;
    asm("add.rn.f32x2 %0, %1, %2;" : "=l"(o) : "l"(a), "l"(b));
    return o;
}

// spread low 4 mask bits into 4 byte-lanes (for packed u8 spike counters)
static __device__ __forceinline__ unsigned spread4(unsigned m) {
    return ((m & 0xFu) * 0x00204081u) & 0x01010101u;
}

// horizontal byte-sum of a packed u8 word (dp4a with all-ones, unsigned)
static __device__ __forceinline__ unsigned bytesum(unsigned v, unsigned c) {
    unsigned ones = 0x01010101u;
    unsigned r;
    asm("dp4a.u32.u32 %0, %1, %2, %3;" : "=r"(r) : "r"(v), "r"(ones), "r"(c));
    return r;
}

// exclusive scan over 512 threads (16 warps); returns total to all threads
static __device__ __forceinline__ void block_scan(int v, int tid, int* s_warp,
                                                  int& excl, int& total) {
    int lane = tid & 31, wid = tid >> 5;
    int x = v;
#pragma unroll
    for (int o = 1; o < 32; o <<= 1) {
        int y = __shfl_up_sync(0xffffffffu, x, o);
        if (lane >= o) x += y;
    }
    __syncthreads();
    if (lane == 31) s_warp[wid] = x;
    __syncthreads();
    int pre = 0, tot = 0;
#pragma unroll
    for (int w = 0; w < 16; w++) {
        int sw = s_warp[w];
        pre += (w < wid) ? sw : 0;
        tot += sw;
    }
    excl = pre + x - v;
    total = tot;
}

// membrane update + spike-mask for one unit across G samples; el uniform/unit
static __device__ __forceinline__ unsigned upd_unit(float m[G], const float* d,
                                                    bool el, unsigned prev) {
    unsigned mask = 0;
    if (el) {
#pragma unroll
        for (int g = 0; g < G; g++) {
            float base = ((prev >> g) & 1) ? 0.0f : m[g] * 0.5f;
            float nm = base + d[g];
            m[g] = nm;
            if (nm > 0.5f) mask |= 1u << g;
        }
    }
    return mask;
}

// union-row gather: acc[g] (packed f32x2 over 2 units) += W rows of spiking h
static __device__ __forceinline__ void gather(const unsigned* __restrict__ list,
                                              int cnt,
                                              const float* __restrict__ WT,
                                              int tid, unsigned long long bias,
                                              unsigned long long acc[G]) {
#pragma unroll
    for (int g = 0; g < G; g++) acc[g] = bias;
    if (cnt <= 0) return;
    const unsigned long long* base =
        reinterpret_cast<const unsigned long long*>(WT) + tid;
    unsigned e0 = list[0];
    unsigned long long w0 = __ldg(base + ((e0 & 1023u) << 9));
    for (int i = 0; i < cnt; i++) {
        unsigned e = e0;
        unsigned long long wv = w0;
        if (i + 1 < cnt) {
            e0 = list[i + 1];
            w0 = __ldg(base + ((e0 & 1023u) << 9));
        }
        unsigned m = e >> 10;  // warp-uniform 8-bit sample mask
        if (m & 1u)   acc[0] = addf32x2(acc[0], wv);
        if (m & 2u)   acc[1] = addf32x2(acc[1], wv);
        if (m & 4u)   acc[2] = addf32x2(acc[2], wv);
        if (m & 8u)   acc[3] = addf32x2(acc[3], wv);
        if (m & 16u)  acc[4] = addf32x2(acc[4], wv);
        if (m & 32u)  acc[5] = addf32x2(acc[5], wv);
        if (m & 64u)  acc[6] = addf32x2(acc[6], wv);
        if (m & 128u) acc[7] = addf32x2(acc[7], wv);
    }
}

union F2U { unsigned long long u; float2 f; };

// ---------------------------------------------------------------------------
__global__ void __launch_bounds__(NTHR) snn_kernel(
    const float* __restrict__ input,
    const float* __restrict__ W1, const float* __restrict__ b1,
    const float* __restrict__ b2, const float* __restrict__ b3,
    const float* __restrict__ W4, const float* __restrict__ b4,
    float* __restrict__ out) {
    __shared__ unsigned listA[HID];
    __shared__ unsigned listB[HID];
    __shared__ int s_warp[16];
    __shared__ float xsh[G * 8];
    __shared__ float4 s_red4[16];

    const int tid = threadIdx.x;
    const int n0 = blockIdx.x * G;
    const int hA = 2 * tid, hB = 2 * tid + 1;

    // per-unit timestep phase: u = (t - h) mod 98, tracked incrementally
    int uA = (98 - (hA % 98)) % 98;
    int uB = (98 - (hB % 98)) % 98;
    int r3A = uA % 3, r3B = uB % 3;

    float m1a[G] = {0}, m1b[G] = {0}, m2a[G] = {0}, m2b[G] = {0},
          m3a[G] = {0}, m3b[G] = {0};
    unsigned p1a = 0, p1b = 0, p2a = 0, p2b = 0, p3a = 0, p3b = 0;
    unsigned ss1al = 0, ss1ah = 0, ss1bl = 0, ss1bh = 0;
    unsigned ss2al = 0, ss2ah = 0, ss2bl = 0, ss2bh = 0;
    unsigned ss3al = 0, ss3ah = 0, ss3bl = 0, ss3bh = 0;

    const float b1a = __ldg(b1 + hA), b1v = __ldg(b1 + hB);
    F2U bp2, bp3;
    bp2.f = make_float2(__ldg(b2 + hA), __ldg(b2 + hB));
    bp3.f = make_float2(__ldg(b3 + hA), __ldg(b3 + hB));

    float w1a[8], w1b[8];
#pragma unroll
    for (int i = 0; i < 8; i++) {
        w1a[i] = __ldg(W1 + hA * 8 + i);
        w1b[i] = __ldg(W1 + hB * 8 + i);
    }

    // drive1 is constant for t >= 12 (start = 776): precompute
    float dc_a[G], dc_b[G];
    if (tid < G * 8)
        xsh[tid] = __ldg(input + (n0 + (tid >> 3)) * 784 + 776 + (tid & 7));
    __syncthreads();
#pragma unroll
    for (int g = 0; g < G; g++) {
        float sa = b1a, sb = b1v;
#pragma unroll
        for (int i = 0; i < 8; i++) {
            float x = xsh[g * 8 + i];
            sa += x * w1a[i];
            sb += x * w1b[i];
        }
        dc_a[g] = sa;
        dc_b[g] = sb;
    }
    __syncthreads();

    for (int t = 0; t < TSTEPS; t++) {
        // ---------- layer 1 drive ----------
        float d1a[G], d1b[G];
        if (t < 12) {
            if (tid < G * 8)
                xsh[tid] =
                    __ldg(input + (n0 + (tid >> 3)) * 784 + t * 8 + (tid & 7));
            __syncthreads();
#pragma unroll
            for (int g = 0; g < G; g++) {
                float sa = b1a, sb = b1v;
#pragma unroll
                for (int i = 0; i < 8; i++) {
                    float x = xsh[g * 8 + i];
                    sa += x * w1a[i];
                    sb += x * w1b[i];
                }
                d1a[g] = sa;
                d1b[g] = sb;
            }
            __syncthreads();
        } else {
#pragma unroll
            for (int g = 0; g < G; g++) {
                d1a[g] = dc_a[g];
                d1b[g] = dc_b[g];
            }
        }

        // ---------- layer 1 update (cycle 2) ----------
        unsigned mA = upd_unit(m1a, d1a, (uA & 1) == 0, p1a);
        unsigned mB = upd_unit(m1b, d1b, (uB & 1) == 0, p1b);
        p1a = mA; p1b = mB;
        ss1al += spread4(mA); ss1ah += spread4(mA >> 4);
        ss1bl += spread4(mB); ss1bh += spread4(mB >> 4);

        int excl, cnt;
        block_scan((mA ? 1 : 0) + (mB ? 1 : 0), tid, s_warp, excl, cnt);
        {
            int p = excl;
            if (mA) listA[p++] = (mA << 10) | (unsigned)hA;
            if (mB) listA[p] = (mB << 10) | (unsigned)hB;
        }
        __syncthreads();

        // ---------- layer 2: gather + update (cycle 3) ----------
        unsigned long long acc[G];
        gather(listA, cnt, g_W2T, tid, bp2.u, acc);
        float d2a[G], d2b[G];
#pragma unroll
        for (int g = 0; g < G; g++) {
            F2U u; u.u = acc[g];
            d2a[g] = u.f.x; d2b[g] = u.f.y;
        }
        mA = upd_unit(m2a, d2a, r3A == 0, p2a);
        mB = upd_unit(m2b, d2b, r3B == 0, p2b);
        p2a = mA; p2b = mB;
        ss2al += spread4(mA); ss2ah += spread4(mA >> 4);
        ss2bl += spread4(mB); ss2bh += spread4(mB >> 4);

        block_scan((mA ? 1 : 0) + (mB ? 1 : 0), tid, s_warp, excl, cnt);
        {
            int p = excl;
            if (mA) listB[p++] = (mA << 10) | (unsigned)hA;
            if (mB) listB[p] = (mB << 10) | (unsigned)hB;
        }
        __syncthreads();

        // ---------- layer 3: gather + update (cycle 4) ----------
        gather(listB, cnt, g_W3T, tid, bp3.u, acc);
        float d3a[G], d3b[G];
#pragma unroll
        for (int g = 0; g < G; g++) {
            F2U u; u.u = acc[g];
            d3a[g] = u.f.x; d3b[g] = u.f.y;
        }
        mA = upd_unit(m3a, d3a, (uA & 3) == 0, p3a);
        mB = upd_unit(m3b, d3b, (uB & 3) == 0, p3b);
        p3a = mA; p3b = mB;
        ss3al += spread4(mA); ss3ah += spread4(mA >> 4);
        ss3bl += spread4(mB); ss3bh += spread4(mB >> 4);

        // advance phases
        if (++uA == 98) { uA = 0; r3A = 0; } else if (++r3A == 3) r3A = 0;
        if (++uB == 98) { uB = 0; r3B = 0; } else if (++r3B == 3) r3B = 0;
    }

    // ------------------------- epilogue -------------------------
    float s3A[G], s3B[G];
#pragma unroll
    for (int g = 0; g < 4; g++) {
        s3A[g]     = (float)((ss3al >> (8 * g)) & 255u);
        s3A[g + 4] = (float)((ss3ah >> (8 * g)) & 255u);
        s3B[g]     = (float)((ss3bl >> (8 * g)) & 255u);
        s3B[g + 4] = (float)((ss3bh >> (8 * g)) & 255u);
    }

    // hidden_spk = ss / 98
#pragma unroll
    for (int g = 0; g < G; g++) {
        float a1 = (float)((g < 4 ? (ss1al >> (8 * g)) : (ss1ah >> (8 * (g - 4)))) & 255u);
        float c1 = (float)((g < 4 ? (ss1bl >> (8 * g)) : (ss1bh >> (8 * (g - 4)))) & 255u);
        float a2 = (float)((g < 4 ? (ss2al >> (8 * g)) : (ss2ah >> (8 * (g - 4)))) & 255u);
        float c2 = (float)((g < 4 ? (ss2bl >> (8 * g)) : (ss2bh >> (8 * (g - 4)))) & 255u);
        const float inv = 1.0f / 98.0f;
        float2* o1 = reinterpret_cast<float2*>(out + 10240 + 0 * 1048576 +
                                               (n0 + g) * HID + hA);
        float2* o2 = reinterpret_cast<float2*>(out + 10240 + 1 * 1048576 +
                                               (n0 + g) * HID + hA);
        float2* o3 = reinterpret_cast<float2*>(out + 10240 + 2 * 1048576 +
                                               (n0 + g) * HID + hA);
        *o1 = make_float2(a1 * inv, c1 * inv);
        *o2 = make_float2(a2 * inv, c2 * inv);
        *o3 = make_float2(s3A[g] * inv, s3B[g] * inv);
    }

    const int lane = tid & 31, wid = tid >> 5;

    // outputs[n] = (ss3 @ W4^T)/98 + b4
    for (int o = 0; o < 10; o++) {
        float wa = __ldg(W4 + o * HID + hA);
        float wb = __ldg(W4 + o * HID + hB);
#pragma unroll
        for (int half = 0; half < 2; half++) {
            float4 v;
            v.x = s3A[half * 4 + 0] * wa + s3B[half * 4 + 0] * wb;
            v.y = s3A[half * 4 + 1] * wa + s3B[half * 4 + 1] * wb;
            v.z = s3A[half * 4 + 2] * wa + s3B[half * 4 + 2] * wb;
            v.w = s3A[half * 4 + 3] * wa + s3B[half * 4 + 3] * wb;
#pragma unroll
            for (int off = 16; off > 0; off >>= 1) {
                v.x += __shfl_down_sync(0xffffffffu, v.x, off);
                v.y += __shfl_down_sync(0xffffffffu, v.y, off);
                v.z += __shfl_down_sync(0xffffffffu, v.z, off);
                v.w += __shfl_down_sync(0xffffffffu, v.w, off);
            }
            if (lane == 0) s_red4[wid] = v;
            __syncthreads();
            if (tid == 0) {
                float4 s = make_float4(0, 0, 0, 0);
#pragma unroll
                for (int w = 0; w < 16; w++) {
                    s.x += s_red4[w].x; s.y += s_red4[w].y;
                    s.z += s_red4[w].z; s.w += s_red4[w].w;
                }
                float bo = __ldg(b4 + o);
                out[(n0 + half * 4 + 0) * 10 + o] = s.x / 98.0f + bo;
                out[(n0 + half * 4 + 1) * 10 + o] = s.y / 98.0f + bo;
                out[(n0 + half * 4 + 2) * 10 + o] = s.z / 98.0f + bo;
                out[(n0 + half * 4 + 3) * 10 + o] = s.w / 98.0f + bo;
            }
            __syncthreads();
        }
    }

    // layer firing-rate sums (packed u8 -> integer via dp4a.u32.u32)
    unsigned c1 = 0, c2 = 0, c3 = 0;
    c1 = bytesum(ss1al, c1); c1 = bytesum(ss1ah, c1);
    c1 = bytesum(ss1bl, c1); c1 = bytesum(ss1bh, c1);
    c2 = bytesum(ss2al, c2); c2 = bytesum(ss2ah, c2);
    c2 = bytesum(ss2bl, c2); c2 = bytesum(ss2bh, c2);
    c3 = bytesum(ss3al, c3); c3 = bytesum(ss3ah, c3);
    c3 = bytesum(ss3bl, c3); c3 = bytesum(ss3bh, c3);
    {
        float4 v = make_float4((float)c1, (float)c2, (float)c3, 0.0f);
#pragma unroll
        for (int off = 16; off > 0; off >>= 1) {
            v.x += __shfl_down_sync(0xffffffffu, v.x, off);
            v.y += __shfl_down_sync(0xffffffffu, v.y, off);
            v.z += __shfl_down_sync(0xffffffffu, v.z, off);
        }
        if (lane == 0) s_red4[wid] = v;
        __syncthreads();
        if (tid == 0) {
            float s0 = 0, s1 = 0, s2 = 0;
#pragma unroll
            for (int w = 0; w < 16; w++) {
                s0 += s_red4[w].x; s1 += s_red4[w].y; s2 += s_red4[w].z;
            }
            atomicAdd(&g_fr[0], s0);
            atomicAdd(&g_fr[1], s1);
            atomicAdd(&g_fr[2], s2);
        }
    }
}

__global__ void finalize_kernel(float* __restrict__ out) {
    if (threadIdx.x < 3)
        out[3155968 + threadIdx.x] = g_fr[threadIdx.x] / 102760448.0f;
}

extern "C" void kernel_launch(void* const* d_in, const int* in_sizes, int n_in,
                              void* d_out, int out_size) {
    const float* input = (const float*)d_in[0];
    const float* W1 = (const float*)d_in[1];
    const float* b1 = (const float*)d_in[2];
    const float* W2 = (const float*)d_in[3];
    const float* b2 = (const float*)d_in[4];
    const float* W3 = (const float*)d_in[5];
    const float* b3 = (const float*)d_in[6];
    const float* W4 = (const float*)d_in[7];
    const float* b4 = (const float*)d_in[8];
    (void)in_sizes; (void)n_in; (void)out_size;

    dim3 pgrid(HID / 32, HID / 32, 2);
    prep_kernel<<<pgrid, dim3(32, 32)>>>(W2, W3);
    snn_kernel<<<NCTA, NTHR>>>(input, W1, b1, b2, b3, W4, b4, (float*)d_out);
    finalize_kernel<<<1, 32>>>((float*)d_out);
}

// round 5
// speedup vs baseline: 1.9433x; 1.6232x over previous
#include <cuda_runtime.h>

#define HID 1024
#define NSAMP 1024
#define TSTEPS 98
#define G 8            // samples per CTA
#define NTHR 512       // threads per CTA; each thread owns units 2*tid, 2*tid+1
#define NCTA (NSAMP / G)

__device__ float g_W2T[HID * HID];
__device__ float g_W3T[HID * HID];
__device__ float g_fr[3];

// ---------------------------------------------------------------------------
__global__ void prep_kernel(const float* __restrict__ W2,
                            const float* __restrict__ W3) {
    __shared__ float tile[32][33];
    const float* src = (blockIdx.z == 0) ? W2 : W3;
    float* dst = (blockIdx.z == 0) ? g_W2T : g_W3T;
    int bx = blockIdx.x * 32, by = blockIdx.y * 32;
    tile[threadIdx.y][threadIdx.x] = src[(by + threadIdx.y) * HID + bx + threadIdx.x];
    __syncthreads();
    dst[(bx + threadIdx.y) * HID + by + threadIdx.x] = tile[threadIdx.x][threadIdx.y];
    if (blockIdx.x == 0 && blockIdx.y == 0 && blockIdx.z == 0 &&
        threadIdx.y == 0 && threadIdx.x < 3)
        g_fr[threadIdx.x] = 0.0f;
}

// ---------------------------------------------------------------------------
static __device__ __forceinline__ unsigned long long addf32x2(
    unsigned long long a, unsigned long long b) {
    unsigned long long o;
    asm("add.rn.f32x2 %0, %1, %2;" : "=l"(o) : "l"(a), "l"(b));
    return o;
}

static __device__ __forceinline__ unsigned spread4(unsigned m) {
    return ((m & 0xFu) * 0x00204081u) & 0x01010101u;
}

static __device__ __forceinline__ unsigned bytesum(unsigned v, unsigned c) {
    unsigned ones = 0x01010101u;
    unsigned r;
    asm("dp4a.u32.u32 %0, %1, %2, %3;" : "=r"(r) : "r"(v), "r"(ones), "r"(c));
    return r;
}

// exclusive scan over 512 threads (16 warps); returns total to all threads
static __device__ __forceinline__ void block_scan(int v, int tid, int* s_warp,
                                                  int& excl, int& total) {
    int lane = tid & 31, wid = tid >> 5;
    int x = v;
#pragma unroll
    for (int o = 1; o < 32; o <<= 1) {
        int y = __shfl_up_sync(0xffffffffu, x, o);
        if (lane >= o) x += y;
    }
    __syncthreads();
    if (lane == 31) s_warp[wid] = x;
    __syncthreads();
    int pre = 0, tot = 0;
#pragma unroll
    for (int w = 0; w < 16; w++) {
        int sw = s_warp[w];
        pre += (w < wid) ? sw : 0;
        tot += sw;
    }
    excl = pre + x - v;
    total = tot;
}

static __device__ __forceinline__ unsigned upd_unit(float m[G], const float* d,
                                                    bool el, unsigned prev) {
    unsigned mask = 0;
    if (el) {
#pragma unroll
        for (int g = 0; g < G; g++) {
            float base = ((prev >> g) & 1) ? 0.0f : m[g] * 0.5f;
            float nm = base + d[g];
            m[g] = nm;
            if (nm > 0.5f) mask |= 1u << g;
        }
    }
    return mask;
}

// 8 predicated packed adds for one row (mask in bits [10:18) of e)
#define ACC8(e, wv)                                          \
    do {                                                     \
        unsigned _m = (e) >> 10;                             \
        if (_m & 1u)   acc[0] = addf32x2(acc[0], (wv));      \
        if (_m & 2u)   acc[1] = addf32x2(acc[1], (wv));      \
        if (_m & 4u)   acc[2] = addf32x2(acc[2], (wv));      \
        if (_m & 8u)   acc[3] = addf32x2(acc[3], (wv));      \
        if (_m & 16u)  acc[4] = addf32x2(acc[4], (wv));      \
        if (_m & 32u)  acc[5] = addf32x2(acc[5], (wv));      \
        if (_m & 64u)  acc[6] = addf32x2(acc[6], (wv));      \
        if (_m & 128u) acc[7] = addf32x2(acc[7], (wv));      \
    } while (0)

// union-row gather, 4-deep software pipeline (4 rows in flight per warp)
static __device__ __forceinline__ void gather(const unsigned* __restrict__ list,
                                              int cnt,
                                              const float* __restrict__ WT,
                                              int tid, unsigned long long bias,
                                              unsigned long long acc[G]) {
#pragma unroll
    for (int g = 0; g < G; g++) acc[g] = bias;
    const unsigned long long* base =
        reinterpret_cast<const unsigned long long*>(WT) + tid;
    const int nb = cnt >> 2;  // full blocks of 4
    if (nb > 0) {
        uint4 c = *reinterpret_cast<const uint4*>(list);
        unsigned e0 = c.x, e1 = c.y, e2 = c.z, e3 = c.w;
        unsigned long long w0 = __ldg(base + ((e0 & 1023u) << 9));
        unsigned long long w1 = __ldg(base + ((e1 & 1023u) << 9));
        unsigned long long w2 = __ldg(base + ((e2 & 1023u) << 9));
        unsigned long long w3 = __ldg(base + ((e3 & 1023u) << 9));
        for (int b = 0; b < nb; b++) {
            unsigned f0 = e0, f1 = e1, f2 = e2, f3 = e3;
            unsigned long long v0 = w0, v1 = w1, v2 = w2, v3 = w3;
            if (b + 1 < nb) {
                uint4 n = *reinterpret_cast<const uint4*>(list + 4 * (b + 1));
                e0 = n.x; e1 = n.y; e2 = n.z; e3 = n.w;
                w0 = __ldg(base + ((e0 & 1023u) << 9));
                w1 = __ldg(base + ((e1 & 1023u) << 9));
                w2 = __ldg(base + ((e2 & 1023u) << 9));
                w3 = __ldg(base + ((e3 & 1023u) << 9));
            }
            ACC8(f0, v0);
            ACC8(f1, v1);
            ACC8(f2, v2);
            ACC8(f3, v3);
        }
    }
    for (int i = nb << 2; i < cnt; i++) {
        unsigned e = list[i];
        unsigned long long wv = __ldg(base + ((e & 1023u) << 9));
        ACC8(e, wv);
    }
}

union F2U { unsigned long long u; float2 f; };

// ---------------------------------------------------------------------------
__global__ void __launch_bounds__(NTHR) snn_kernel(
    const float* __restrict__ input,
    const float* __restrict__ W1, const float* __restrict__ b1,
    const float* __restrict__ b2, const float* __restrict__ b3,
    const float* __restrict__ W4, const float* __restrict__ b4,
    float* __restrict__ out) {
    __shared__ __align__(16) unsigned listA[HID];
    __shared__ __align__(16) unsigned listB[HID];
    __shared__ int s_warp[16];
    __shared__ float xsh[G * 8];
    __shared__ float4 s_red4[16];
    __shared__ unsigned long long dcsh[NTHR * G];  // 32KB: const layer-1 drive

    const int tid = threadIdx.x;
    const int n0 = blockIdx.x * G;
    const int hA = 2 * tid, hB = 2 * tid + 1;

    int uA = (98 - (hA % 98)) % 98;
    int uB = (98 - (hB % 98)) % 98;
    int r3A = uA % 3, r3B = uB % 3;

    float m1a[G] = {0}, m1b[G] = {0}, m2a[G] = {0}, m2b[G] = {0},
          m3a[G] = {0}, m3b[G] = {0};
    unsigned p1a = 0, p1b = 0, p2a = 0, p2b = 0, p3a = 0, p3b = 0;
    unsigned ss1al = 0, ss1ah = 0, ss1bl = 0, ss1bh = 0;
    unsigned ss2al = 0, ss2ah = 0, ss2bl = 0, ss2bh = 0;
    unsigned ss3al = 0, ss3ah = 0, ss3bl = 0, ss3bh = 0;

    F2U bp2, bp3;
    bp2.f = make_float2(__ldg(b2 + hA), __ldg(b2 + hB));
    bp3.f = make_float2(__ldg(b3 + hA), __ldg(b3 + hB));

    const float4* W14 = reinterpret_cast<const float4*>(W1);

    // constant layer-1 drive (t >= 12, input slice fixed at 776): to SMEM
    if (tid < G * 8)
        xsh[tid] = __ldg(input + (n0 + (tid >> 3)) * 784 + 776 + (tid & 7));
    __syncthreads();
    {
        float4 wa0 = __ldg(W14 + hA * 2), wa1 = __ldg(W14 + hA * 2 + 1);
        float4 wb0 = __ldg(W14 + hB * 2), wb1 = __ldg(W14 + hB * 2 + 1);
        float ba = __ldg(b1 + hA), bb = __ldg(b1 + hB);
#pragma unroll
        for (int g = 0; g < G; g++) {
            const float* x = &xsh[g * 8];
            float sa = ba + x[0] * wa0.x + x[1] * wa0.y + x[2] * wa0.z +
                       x[3] * wa0.w + x[4] * wa1.x + x[5] * wa1.y +
                       x[6] * wa1.z + x[7] * wa1.w;
            float sb = bb + x[0] * wb0.x + x[1] * wb0.y + x[2] * wb0.z +
                       x[3] * wb0.w + x[4] * wb1.x + x[5] * wb1.y +
                       x[6] * wb1.z + x[7] * wb1.w;
            F2U u;
            u.f = make_float2(sa, sb);
            dcsh[g * NTHR + tid] = u.u;
        }
    }
    __syncthreads();

    for (int t = 0; t < TSTEPS; t++) {
        // ---------- layer 1 drive ----------
        float d1a[G], d1b[G];
        if (t < 12) {
            if (tid < G * 8)
                xsh[tid] =
                    __ldg(input + (n0 + (tid >> 3)) * 784 + t * 8 + (tid & 7));
            __syncthreads();
            float4 wa0 = __ldg(W14 + hA * 2), wa1 = __ldg(W14 + hA * 2 + 1);
            float4 wb0 = __ldg(W14 + hB * 2), wb1 = __ldg(W14 + hB * 2 + 1);
            float ba = __ldg(b1 + hA), bb = __ldg(b1 + hB);
#pragma unroll
            for (int g = 0; g < G; g++) {
                const float* x = &xsh[g * 8];
                d1a[g] = ba + x[0] * wa0.x + x[1] * wa0.y + x[2] * wa0.z +
                         x[3] * wa0.w + x[4] * wa1.x + x[5] * wa1.y +
                         x[6] * wa1.z + x[7] * wa1.w;
                d1b[g] = bb + x[0] * wb0.x + x[1] * wb0.y + x[2] * wb0.z +
                         x[3] * wb0.w + x[4] * wb1.x + x[5] * wb1.y +
                         x[6] * wb1.z + x[7] * wb1.w;
            }
            __syncthreads();
        } else {
#pragma unroll
            for (int g = 0; g < G; g++) {
                F2U u;
                u.u = dcsh[g * NTHR + tid];
                d1a[g] = u.f.x;
                d1b[g] = u.f.y;
            }
        }

        // ---------- layer 1 update (cycle 2) ----------
        unsigned mA = upd_unit(m1a, d1a, (uA & 1) == 0, p1a);
        unsigned mB = upd_unit(m1b, d1b, (uB & 1) == 0, p1b);
        p1a = mA; p1b = mB;
        ss1al += spread4(mA); ss1ah += spread4(mA >> 4);
        ss1bl += spread4(mB); ss1bh += spread4(mB >> 4);

        int excl, cnt;
        block_scan((mA ? 1 : 0) + (mB ? 1 : 0), tid, s_warp, excl, cnt);
        {
            int p = excl;
            if (mA) listA[p++] = (mA << 10) | (unsigned)hA;
            if (mB) listA[p] = (mB << 10) | (unsigned)hB;
        }
        __syncthreads();

        // ---------- layer 2: gather + update (cycle 3) ----------
        unsigned long long acc[G];
        gather(listA, cnt, g_W2T, tid, bp2.u, acc);
        float d2a[G], d2b[G];
#pragma unroll
        for (int g = 0; g < G; g++) {
            F2U u; u.u = acc[g];
            d2a[g] = u.f.x; d2b[g] = u.f.y;
        }
        mA = upd_unit(m2a, d2a, r3A == 0, p2a);
        mB = upd_unit(m2b, d2b, r3B == 0, p2b);
        p2a = mA; p2b = mB;
        ss2al += spread4(mA); ss2ah += spread4(mA >> 4);
        ss2bl += spread4(mB); ss2bh += spread4(mB >> 4);

        block_scan((mA ? 1 : 0) + (mB ? 1 : 0), tid, s_warp, excl, cnt);
        {
            int p = excl;
            if (mA) listB[p++] = (mA << 10) | (unsigned)hA;
            if (mB) listB[p] = (mB << 10) | (unsigned)hB;
        }
        __syncthreads();

        // ---------- layer 3: gather + update (cycle 4) ----------
        gather(listB, cnt, g_W3T, tid, bp3.u, acc);
        float d3a[G], d3b[G];
#pragma unroll
        for (int g = 0; g < G; g++) {
            F2U u; u.u = acc[g];
            d3a[g] = u.f.x; d3b[g] = u.f.y;
        }
        mA = upd_unit(m3a, d3a, (uA & 3) == 0, p3a);
        mB = upd_unit(m3b, d3b, (uB & 3) == 0, p3b);
        p3a = mA; p3b = mB;
        ss3al += spread4(mA); ss3ah += spread4(mA >> 4);
        ss3bl += spread4(mB); ss3bh += spread4(mB >> 4);

        if (++uA == 98) { uA = 0; r3A = 0; } else if (++r3A == 3) r3A = 0;
        if (++uB == 98) { uB = 0; r3B = 0; } else if (++r3B == 3) r3B = 0;
    }

    // ------------------------- epilogue -------------------------
    float s3A[G], s3B[G];
#pragma unroll
    for (int g = 0; g < 4; g++) {
        s3A[g]     = (float)((ss3al >> (8 * g)) & 255u);
        s3A[g + 4] = (float)((ss3ah >> (8 * g)) & 255u);
        s3B[g]     = (float)((ss3bl >> (8 * g)) & 255u);
        s3B[g + 4] = (float)((ss3bh >> (8 * g)) & 255u);
    }

#pragma unroll
    for (int g = 0; g < G; g++) {
        float a1 = (float)((g < 4 ? (ss1al >> (8 * g)) : (ss1ah >> (8 * (g - 4)))) & 255u);
        float c1 = (float)((g < 4 ? (ss1bl >> (8 * g)) : (ss1bh >> (8 * (g - 4)))) & 255u);
        float a2 = (float)((g < 4 ? (ss2al >> (8 * g)) : (ss2ah >> (8 * (g - 4)))) & 255u);
        float c2 = (float)((g < 4 ? (ss2bl >> (8 * g)) : (ss2bh >> (8 * (g - 4)))) & 255u);
        const float inv = 1.0f / 98.0f;
        float2* o1 = reinterpret_cast<float2*>(out + 10240 + 0 * 1048576 +
                                               (n0 + g) * HID + hA);
        float2* o2 = reinterpret_cast<float2*>(out + 10240 + 1 * 1048576 +
                                               (n0 + g) * HID + hA);
        float2* o3 = reinterpret_cast<float2*>(out + 10240 + 2 * 1048576 +
                                               (n0 + g) * HID + hA);
        *o1 = make_float2(a1 * inv, c1 * inv);
        *o2 = make_float2(a2 * inv, c2 * inv);
        *o3 = make_float2(s3A[g] * inv, s3B[g] * inv);
    }

    const int lane = tid & 31, wid = tid >> 5;

    for (int o = 0; o < 10; o++) {
        float wa = __ldg(W4 + o * HID + hA);
        float wb = __ldg(W4 + o * HID + hB);
#pragma unroll
        for (int half = 0; half < 2; half++) {
            float4 v;
            v.x = s3A[half * 4 + 0] * wa + s3B[half * 4 + 0] * wb;
            v.y = s3A[half * 4 + 1] * wa + s3B[half * 4 + 1] * wb;
            v.z = s3A[half * 4 + 2] * wa + s3B[half * 4 + 2] * wb;
            v.w = s3A[half * 4 + 3] * wa + s3B[half * 4 + 3] * wb;
#pragma unroll
            for (int off = 16; off > 0; off >>= 1) {
                v.x += __shfl_down_sync(0xffffffffu, v.x, off);
                v.y += __shfl_down_sync(0xffffffffu, v.y, off);
                v.z += __shfl_down_sync(0xffffffffu, v.z, off);
                v.w += __shfl_down_sync(0xffffffffu, v.w, off);
            }
            if (lane == 0) s_red4[wid] = v;
            __syncthreads();
            if (tid == 0) {
                float4 s = make_float4(0, 0, 0, 0);
#pragma unroll
                for (int w = 0; w < 16; w++) {
                    s.x += s_red4[w].x; s.y += s_red4[w].y;
                    s.z += s_red4[w].z; s.w += s_red4[w].w;
                }
                float bo = __ldg(b4 + o);
                out[(n0 + half * 4 + 0) * 10 + o] = s.x / 98.0f + bo;
                out[(n0 + half * 4 + 1) * 10 + o] = s.y / 98.0f + bo;
                out[(n0 + half * 4 + 2) * 10 + o] = s.z / 98.0f + bo;
                out[(n0 + half * 4 + 3) * 10 + o] = s.w / 98.0f + bo;
            }
            __syncthreads();
        }
    }

    unsigned c1 = 0, c2 = 0, c3 = 0;
    c1 = bytesum(ss1al, c1); c1 = bytesum(ss1ah, c1);
    c1 = bytesum(ss1bl, c1); c1 = bytesum(ss1bh, c1);
    c2 = bytesum(ss2al, c2); c2 = bytesum(ss2ah, c2);
    c2 = bytesum(ss2bl, c2); c2 = bytesum(ss2bh, c2);
    c3 = bytesum(ss3al, c3); c3 = bytesum(ss3ah, c3);
    c3 = bytesum(ss3bl, c3); c3 = bytesum(ss3bh, c3);
    {
        float4 v = make_float4((float)c1, (float)c2, (float)c3, 0.0f);
#pragma unroll
        for (int off = 16; off > 0; off >>= 1) {
            v.x += __shfl_down_sync(0xffffffffu, v.x, off);
            v.y += __shfl_down_sync(0xffffffffu, v.y, off);
            v.z += __shfl_down_sync(0xffffffffu, v.z, off);
        }
        if (lane == 0) s_red4[wid] = v;
        __syncthreads();
        if (tid == 0) {
            float s0 = 0, s1 = 0, s2 = 0;
#pragma unroll
            for (int w = 0; w < 16; w++) {
                s0 += s_red4[w].x; s1 += s_red4[w].y; s2 += s_red4[w].z;
            }
            atomicAdd(&g_fr[0], s0);
            atomicAdd(&g_fr[1], s1);
            atomicAdd(&g_fr[2], s2);
        }
    }
}

__global__ void finalize_kernel(float* __restrict__ out) {
    if (threadIdx.x < 3)
        out[3155968 + threadIdx.x] = g_fr[threadIdx.x] / 102760448.0f;
}

extern "C" void kernel_launch(void* const* d_in, const int* in_sizes, int n_in,
                              void* d_out, int out_size) {
    const float* input = (const float*)d_in[0];
    const float* W1 = (const float*)d_in[1];
    const float* b1 = (const float*)d_in[2];
    const float* W2 = (const float*)d_in[3];
    const float* b2 = (const float*)d_in[4];
    const float* W3 = (const float*)d_in[5];
    const float* b3 = (const float*)d_in[6];
    const float* W4 = (const float*)d_in[7];
    const float* b4 = (const float*)d_in[8];
    (void)in_sizes; (void)n_in; (void)out_size;

    dim3 pgrid(HID / 32, HID / 32, 2);
    prep_kernel<<<pgrid, dim3(32, 32)>>>(W2, W3);
    snn_kernel<<<NCTA, NTHR>>>(input, W1, b1, b2, b3, W4, b4, (float*)d_out);
    finalize_kernel<<<1, 32>>>((float*)d_out);
}